// round 8
// baseline (speedup 1.0000x reference)
#include <cuda_runtime.h>
#include <cuda_bf16.h>
#include <cstdint>

// ---------------------------------------------------------------------------
//   y   = W @ x + b   (oc=128, cin=128, vox=186624)
//   out = leaky_0.2( y * (y + att[c,l,pp]/nz[c,l] + 1) )
// GEMM on mma.sync m16n8k16 (bf16) via 3-way split: Wh*xh + Wh*xl + Wl*xh
// R8: two independent 8-warp pipelines per CTA (named barriers, per-group
//     double-buffered x tiles) to break phase lockstep; else same as R7.
// ---------------------------------------------------------------------------

#define CIN    128
#define COUT   128
#define HWDIM  5184
#define NVOX   186624
#define PATCH  9
#define PPSQ   81
#define NW     576
#define LPATCH 2304

#define TILE_V  128
#define NTILES  1458          // NVOX / TILE_V
#define GRID    148
#define THREADS 512

// dynamic smem (bytes):
//   group g (g=0,1): stage s (s=0,1): xh 16KB + xl 16KB @ g*65536 + s*32768
//   W: Wh 32KB + Wl 32KB @ 131072
#define SM_W  131072
#define SMEM_TOTAL 196608

__device__ __align__(16) unsigned short g_Wsw[32768];   // [Wh][Wl], swizzled
__device__ __align__(16) unsigned short g_atts[COUT * LPATCH * PPSQ]; // bf16 att/nz

// ---------------------------------------------------------------------------
// helpers
// ---------------------------------------------------------------------------
__device__ __forceinline__ uint32_t smem_u32(const void* p) {
    uint32_t a;
    asm("{ .reg .u64 t; cvta.to.shared.u64 t, %1; cvt.u32.u64 %0, t; }"
        : "=r"(a) : "l"(p));
    return a;
}
__device__ __forceinline__ uint32_t pack_bf16x2(float lo, float hi) {
    uint32_t r;
    asm("cvt.rn.bf16x2.f32 %0, %1, %2;" : "=r"(r) : "f"(hi), "f"(lo));
    return r;
}
__device__ __forceinline__ int redux_add(int v) {
    int r;
    asm("redux.sync.add.s32 %0, %1, 0xffffffff;" : "=r"(r) : "r"(v));
    return r;
}
__device__ __forceinline__ void sts64(uint32_t addr, uint32_t a, uint32_t b) {
    asm volatile("st.shared.v2.u32 [%0], {%1, %2};"
                 :: "r"(addr), "r"(a), "r"(b) : "memory");
}
__device__ __forceinline__ void ldsm_x4(uint32_t addr, uint32_t* r) {
    asm volatile("ldmatrix.sync.aligned.m8n8.x4.shared.b16 {%0,%1,%2,%3}, [%4];"
                 : "=r"(r[0]), "=r"(r[1]), "=r"(r[2]), "=r"(r[3]) : "r"(addr));
}
__device__ __forceinline__ void ldsm_x4_t(uint32_t addr, uint32_t* r) {
    asm volatile("ldmatrix.sync.aligned.m8n8.x4.trans.shared.b16 {%0,%1,%2,%3}, [%4];"
                 : "=r"(r[0]), "=r"(r[1]), "=r"(r[2]), "=r"(r[3]) : "r"(addr));
}
__device__ __forceinline__ void mma16816(float* d, const uint32_t* a,
                                         uint32_t b0, uint32_t b1) {
    asm volatile(
        "mma.sync.aligned.m16n8k16.row.col.f32.bf16.bf16.f32 "
        "{%0,%1,%2,%3}, {%4,%5,%6,%7}, {%8,%9}, {%0,%1,%2,%3};"
        : "+f"(d[0]), "+f"(d[1]), "+f"(d[2]), "+f"(d[3])
        : "r"(a[0]), "r"(a[1]), "r"(a[2]), "r"(a[3]), "r"(b0), "r"(b1));
}
__device__ __forceinline__ unsigned short ldg_u16(const unsigned short* p) {
    unsigned short v;
    asm volatile("ld.global.nc.u16 %0, [%1];" : "=h"(v) : "l"(p));
    return v;
}
__device__ __forceinline__ float bf2f(unsigned short v) {
    return __uint_as_float((uint32_t)v << 16);
}
__device__ __forceinline__ float sel4(int r, float a, float b, float c, float d) {
    float v = a;
    v = (r == 1) ? b : v;
    v = (r == 2) ? c : v;
    v = (r == 3) ? d : v;
    return v;
}
// W-tile swizzle (256B rows, verified)
__device__ __forceinline__ uint32_t swz(int row, uint32_t colbyte) {
    return (uint32_t)row * 256u + (colbyte ^ (uint32_t)((row & 7) << 4));
}
// named barrier for group g (256 threads)
__device__ __forceinline__ void gbar(int g) {
    asm volatile("bar.sync %0, 256;" :: "r"(g + 1) : "memory");
}

// ---------------------------------------------------------------------------
// Prep: W bf16 hi/lo split (swizzled) + att -> bf16(att/nz) into g_atts.
// ---------------------------------------------------------------------------
__device__ __forceinline__ void process_group(const float4* f, int g, int lane)
{
    int c0 = 0, c1 = 0, c2 = 0, c3 = 0;
#pragma unroll
    for (int p = 0; p < 3; p++) {
        int idx = p * 32 + lane;
        if (idx < 81) {
            float4 q = f[p];
            int e = idx * 4;
            int r0 = (e >= 81) + (e >= 162) + (e >= 243);
            int r3 = (e + 3 >= 81) + (e + 3 >= 162) + (e + 3 >= 243);
            if (r0 == r3) {
                int cnt = (q.x != 0.f) + (q.y != 0.f) + (q.z != 0.f) + (q.w != 0.f);
                c0 += (r0 == 0) ? cnt : 0;
                c1 += (r0 == 1) ? cnt : 0;
                c2 += (r0 == 2) ? cnt : 0;
                c3 += (r0 == 3) ? cnt : 0;
            } else {
                float vv[4] = { q.x, q.y, q.z, q.w };
#pragma unroll
                for (int j = 0; j < 4; j++) {
                    int ej = e + j;
                    int rj = (ej >= 81) + (ej >= 162) + (ej >= 243);
                    int nz = (vv[j] != 0.f);
                    c0 += (rj == 0) ? nz : 0;
                    c1 += (rj == 1) ? nz : 0;
                    c2 += (rj == 2) ? nz : 0;
                    c3 += (rj == 3) ? nz : 0;
                }
            }
        }
    }
    c0 = redux_add(c0); c1 = redux_add(c1);
    c2 = redux_add(c2); c3 = redux_add(c3);
    float i0 = 1.0f / ((float)c0 + 1e-5f);
    float i1 = 1.0f / ((float)c1 + 1e-5f);
    float i2 = 1.0f / ((float)c2 + 1e-5f);
    float i3 = 1.0f / ((float)c3 + 1e-5f);

#pragma unroll
    for (int p = 0; p < 3; p++) {
        int idx = p * 32 + lane;
        if (idx < 81) {
            float4 q = f[p];
            int e = idx * 4;
            int r0 = (e >= 81) + (e >= 162) + (e >= 243);
            int r1 = (e + 1 >= 81) + (e + 1 >= 162) + (e + 1 >= 243);
            int r2 = (e + 2 >= 81) + (e + 2 >= 162) + (e + 2 >= 243);
            int r3 = (e + 3 >= 81) + (e + 3 >= 162) + (e + 3 >= 243);
            float s0 = sel4(r0, i0, i1, i2, i3);
            float s1 = sel4(r1, i0, i1, i2, i3);
            float s2 = sel4(r2, i0, i1, i2, i3);
            float s3 = sel4(r3, i0, i1, i2, i3);
            uint32_t u01 = pack_bf16x2(q.x * s0, q.y * s1);
            uint32_t u23 = pack_bf16x2(q.z * s2, q.w * s3);
            *(uint2*)(g_atts + (size_t)g * 324 + idx * 4) = make_uint2(u01, u23);
        }
    }
}

__global__ __launch_bounds__(256) void prep_kernel(const float* __restrict__ att,
                                                   const float* __restrict__ W)
{
    const int tid = threadIdx.x;
    const int blk = blockIdx.x;

    if (blk < 64) {   // W split
        int idx = blk * 256 + tid;
        int oc = idx >> 7, k = idx & 127;
        float w = W[idx];
        __nv_bfloat16 h = __float2bfloat16(w);
        float hf = __bfloat162float(h);
        __nv_bfloat16 l = __float2bfloat16(w - hf);
        uint32_t off = swz(oc, (uint32_t)(k * 2)) >> 1;
        g_Wsw[off]         = *(unsigned short*)&h;
        g_Wsw[off + 16384] = *(unsigned short*)&l;
    }

    const int wg = (blk * 256 + tid) >> 5;
    const int lane = tid & 31;
    const int g0 = wg * 2;
    const float4* a4a = (const float4*)att + (size_t)g0 * 81;
    const float4* a4b = a4a + 81;

    float4 fa[3], fb[3];
#pragma unroll
    for (int p = 0; p < 3; p++) {
        int idx = p * 32 + lane;
        if (idx < 81) {
            fa[p] = __ldg(a4a + idx);
            fb[p] = __ldg(a4b + idx);
        }
    }
    process_group(fa, g0, lane);
    process_group(fb, g0 + 1, lane);
}

// ---------------------------------------------------------------------------
// Fused persistent kernel: 2 independent 8-warp groups per CTA.
//   group g (wid>>3): vox slice [t*128 + g*64, +64)
//   within group: wr = wid&7, ocb = (wr&3)*32, vhl = (wr>>2)*32 (local vox half)
// ---------------------------------------------------------------------------
struct XFrag { float4 f[8]; };

// warp wr loads k rows [wr*16, wr*16+16) of the group's 64-vox slice
__device__ __forceinline__ void ldg_tile_g(const float* __restrict__ x,
                                           int v0g, int wr, int lane, XFrag& r)
{
    const int k0 = wr * 16 + (lane >> 4);
    const float* xp = x + (size_t)k0 * NVOX + v0g + (lane & 15) * 4;
#pragma unroll
    for (int i = 0; i < 8; i++)
        r.f[i] = *(const float4*)(xp + (size_t)(2 * i) * NVOX);
}

// group buffer: 128 k-rows x 64 vox bf16, 128B rows, chunk xor (k&7)
__device__ __forceinline__ void sts_tile_g(uint32_t bufH, int wr, int lane,
                                           const XFrag& r)
{
    const int kbase = wr * 16 + (lane >> 4);
    const uint32_t voxb = (uint32_t)((lane & 15) * 8);
#pragma unroll
    for (int i = 0; i < 8; i++) {
        const int k = kbase + 2 * i;
        float4 f = r.f[i];
        uint32_t h01 = pack_bf16x2(f.x, f.y);
        uint32_t h23 = pack_bf16x2(f.z, f.w);
        float h0 = __uint_as_float(h01 << 16);
        float h1 = __uint_as_float(h01 & 0xffff0000u);
        float h2 = __uint_as_float(h23 << 16);
        float h3 = __uint_as_float(h23 & 0xffff0000u);
        uint32_t l01 = pack_bf16x2(f.x - h0, f.y - h1);
        uint32_t l23 = pack_bf16x2(f.z - h2, f.w - h3);
        uint32_t addr = bufH + (uint32_t)k * 128u
                      + (voxb ^ (uint32_t)((k & 7) << 4));
        sts64(addr, h01, h23);
        sts64(addr + 16384, l01, l23);   // xl 16KB after xh
    }
}

__global__ __launch_bounds__(THREADS, 1)
void fused_kernel(const float* __restrict__ x,
                  const float* __restrict__ b,
                  float* __restrict__ out)
{
    extern __shared__ __align__(16) char smem[];
    const uint32_t sbase = smem_u32(smem);
    const int tid  = threadIdx.x;
    const int lane = tid & 31;
    const int wid  = tid >> 5;
    const int g    = wid >> 3;          // pipeline group 0/1
    const int wr   = wid & 7;           // warp-in-group

    // load W once (64KB)
    {
        const float4* Wv = (const float4*)g_Wsw;
        float4* sWv = (float4*)(smem + SM_W);
#pragma unroll
        for (int i = 0; i < 8; i++)
            sWv[tid + THREADS * i] = Wv[tid + THREADS * i];
    }

    const int ocb = (wr & 3) * 32;
    const int vhl = (wr >> 2) * 32;     // local vox half within group's 64
    const int ocl = ocb + (lane >> 2);
    const uint32_t gbase = sbase + (uint32_t)g * 65536u;

    // A-side ldmatrix ([oc][k] 256B rows, verified)
    const int aRow = ocb + (lane & 15);
    const uint32_t aSw = (uint32_t)((aRow & 7) << 4);
    const uint32_t aK  = (uint32_t)((lane >> 4) * 16);
    const uint32_t aB  = sbase + SM_W + (uint32_t)aRow * 256u;

    // B-side ldmatrix.trans (group buffer, 128B rows, xor (k&7))
    const int bK = lane & 15;
    uint32_t bOff[2];
#pragma unroll
    for (int nbp = 0; nbp < 2; nbp++) {
        uint32_t voxbyte = (uint32_t)(vhl * 2 + nbp * 32 + (lane >> 4) * 16);
        bOff[nbp] = (uint32_t)bK * 128u
                  + (voxbyte ^ ((uint32_t)(bK & 7) << 4));
    }

    const float bias0a = __ldg(b + ocl);
    const float bias0b = __ldg(b + ocl + 8);
    const float bias1a = __ldg(b + ocl + 16);
    const float bias1b = __ldg(b + ocl + 24);

    // prologue: tile0 into stage 0
    int t = blockIdx.x;
    {
        XFrag r0;
        ldg_tile_g(x, t * TILE_V + g * 64, wr, lane, r0);
        sts_tile_g(gbase, wr, lane, r0);
    }
    __syncthreads();   // covers W + both groups' tile0

    int cur = 0;
    while (true) {
        const int tn = t + GRID;
        const bool has_next = (tn < NTILES);

        // prefetch next x tile into regs
        XFrag rn;
        if (has_next) ldg_tile_g(x, tn * TILE_V + g * 64, wr, lane, rn);

        // prefetch epilogue att values for tile t
        unsigned short avr[2][4][4];
        {
            int l0x[4], p0x[4], l1x[4], p1x[4];
#pragma unroll
            for (int nb = 0; nb < 4; nb++) {
                int v  = t * TILE_V + g * 64 + vhl + 2 * (lane & 3) + nb * 8;
                int d  = v / HWDIM;
                int hw = v - d * HWDIM;
                int id = d / PATCH,  pd = d  - id * PATCH;
                int iw = hw / PATCH, pw = hw - iw * PATCH;
                int l0 = id * NW + iw, p0 = pd * PATCH + pw;
                l0x[nb] = l0; p0x[nb] = p0;
                if (pw == PATCH - 1) { l1x[nb] = l0 + 1; p1x[nb] = pd * PATCH; }
                else                 { l1x[nb] = l0;     p1x[nb] = p0 + 1; }
            }
#pragma unroll
            for (int tt = 0; tt < 2; tt++) {
                const unsigned short* A0 =
                    g_atts + (size_t)(ocl + 16 * tt) * (LPATCH * PPSQ);
                const unsigned short* A1 = A0 + (size_t)8 * (LPATCH * PPSQ);
#pragma unroll
                for (int nb = 0; nb < 4; nb++) {
                    avr[tt][nb][0] = ldg_u16(A0 + l0x[nb] * PPSQ + p0x[nb]);
                    avr[tt][nb][1] = ldg_u16(A0 + l1x[nb] * PPSQ + p1x[nb]);
                    avr[tt][nb][2] = ldg_u16(A1 + l0x[nb] * PPSQ + p0x[nb]);
                    avr[tt][nb][3] = ldg_u16(A1 + l1x[nb] * PPSQ + p1x[nb]);
                }
            }
        }

        // accumulators, init with bias
        float acc[2][4][4];
#pragma unroll
        for (int nb = 0; nb < 4; nb++) {
            acc[0][nb][0] = bias0a; acc[0][nb][1] = bias0a;
            acc[0][nb][2] = bias0b; acc[0][nb][3] = bias0b;
            acc[1][nb][0] = bias1a; acc[1][nb][1] = bias1a;
            acc[1][nb][2] = bias1b; acc[1][nb][3] = bias1b;
        }

        // MMA over 8 k-steps, 3 split terms, 4-wide acc interleave
        const uint32_t bufH = gbase + (uint32_t)cur * 32768u;
        const uint32_t bufL = bufH + 16384u;
#pragma unroll
        for (int ks = 0; ks < 8; ks++) {
            const uint32_t kbA = ((uint32_t)(ks * 32) + aK) ^ aSw;
            uint32_t a0h[4], a1h[4], a0l[4], a1l[4];
            ldsm_x4(aB + kbA,                a0h);
            ldsm_x4(aB + 4096 + kbA,         a1h);
            ldsm_x4(aB + 32768 + kbA,        a0l);
            ldsm_x4(aB + 32768 + 4096 + kbA, a1l);

            const uint32_t krow = (uint32_t)(ks * 2048);   // 16 rows x 128B
#pragma unroll
            for (int nbp = 0; nbp < 2; nbp++) {
                uint32_t bh[4], bl[4];
                ldsm_x4_t(bufH + krow + bOff[nbp], bh);
                ldsm_x4_t(bufL + krow + bOff[nbp], bl);
                float* A00 = acc[0][2 * nbp];
                float* A10 = acc[1][2 * nbp];
                float* A01 = acc[0][2 * nbp + 1];
                float* A11 = acc[1][2 * nbp + 1];
                mma16816(A00, a0h, bh[0], bh[1]);
                mma16816(A10, a1h, bh[0], bh[1]);
                mma16816(A01, a0h, bh[2], bh[3]);
                mma16816(A11, a1h, bh[2], bh[3]);
                mma16816(A00, a0h, bl[0], bl[1]);
                mma16816(A10, a1h, bl[0], bl[1]);
                mma16816(A01, a0h, bl[2], bl[3]);
                mma16816(A11, a1h, bl[2], bl[3]);
                mma16816(A00, a0l, bh[0], bh[1]);
                mma16816(A10, a1l, bh[0], bh[1]);
                mma16816(A01, a0l, bh[2], bh[3]);
                mma16816(A11, a1l, bh[2], bh[3]);
            }
        }

        // store next tile into other stage, then group barrier
        if (has_next) sts_tile_g(gbase + (uint32_t)(cur ^ 1) * 32768u, wr, lane, rn);
        gbar(g);

        // epilogue: regs + STG only
        const int voxbase = t * TILE_V + g * 64 + vhl + 2 * (lane & 3);
#pragma unroll
        for (int tt = 0; tt < 2; tt++) {
            float* o0 = out + (size_t)(ocl + 16 * tt) * NVOX;
            float* o1 = o0 + (size_t)8 * NVOX;
#pragma unroll
            for (int nb = 0; nb < 4; nb++) {
                const int v = voxbase + nb * 8;
                float a00 = bf2f(avr[tt][nb][0]);
                float a01 = bf2f(avr[tt][nb][1]);
                float a10 = bf2f(avr[tt][nb][2]);
                float a11 = bf2f(avr[tt][nb][3]);

                float y;
                float2 r;
                y = acc[tt][nb][0]; r.x = y * (y + a00 + 1.0f);
                r.x = (r.x >= 0.0f) ? r.x : 0.2f * r.x;
                y = acc[tt][nb][1]; r.y = y * (y + a01 + 1.0f);
                r.y = (r.y >= 0.0f) ? r.y : 0.2f * r.y;
                *(float2*)(o0 + v) = r;

                y = acc[tt][nb][2]; r.x = y * (y + a10 + 1.0f);
                r.x = (r.x >= 0.0f) ? r.x : 0.2f * r.x;
                y = acc[tt][nb][3]; r.y = y * (y + a11 + 1.0f);
                r.y = (r.y >= 0.0f) ? r.y : 0.2f * r.y;
                *(float2*)(o1 + v) = r;
            }
        }

        if (!has_next) break;
        t = tn;
        cur ^= 1;
    }
}

// ---------------------------------------------------------------------------
extern "C" void kernel_launch(void* const* d_in, const int* in_sizes, int n_in,
                              void* d_out, int out_size)
{
    (void)in_sizes; (void)n_in; (void)out_size;
    const float* x   = (const float*)d_in[0];
    const float* att = (const float*)d_in[1];
    const float* W   = (const float*)d_in[2];
    const float* b   = (const float*)d_in[3];
    float* out = (float*)d_out;

    prep_kernel<<<4608, 256>>>(att, W);

    cudaFuncSetAttribute(fused_kernel,
                         cudaFuncAttributeMaxDynamicSharedMemorySize,
                         SMEM_TOTAL);
    fused_kernel<<<GRID, THREADS, SMEM_TOTAL>>>(x, b, out);
}

// round 9
// speedup vs baseline: 1.0957x; 1.0957x over previous
#include <cuda_runtime.h>
#include <cuda_bf16.h>
#include <cstdint>

// ---------------------------------------------------------------------------
//   y   = W @ x + b   (oc=128, cin=128, vox=186624)
//   out = leaky_0.2( y * (y + att[c,l,pp]/nz[c,l] + 1) )
// GEMM on mma.sync m16n8k16 (bf16) via 3-way split: Wh*xh + Wh*xl + Wl*xh
// R9: TWO persistent CTAs per SM, split by oc-half (W slice 32KB each),
//     64-vox tiles double-buffered; independent barrier domains overlap
//     LSU-phase of one CTA with tensor-phase of the other.
// ---------------------------------------------------------------------------

#define CIN    128
#define COUT   128
#define HWDIM  5184
#define NVOX   186624
#define PATCH  9
#define PPSQ   81
#define NW     576
#define LPATCH 2304

#define TILE_V  64
#define NT64    2916          // NVOX / 64
#define GRID    296           // 2 CTAs per SM
#define THREADS 256

// per-CTA dynamic smem (bytes):
//   stage s (0,1): xh 16KB @ s*32768, xl 16KB @ s*32768+16384
//   W (this oc-half): Wh 16KB @ 65536, Wl 16KB @ 81920
#define SM_W  65536
#define SMEM_TOTAL 98304

__device__ __align__(16) unsigned short g_Wsw[32768];   // [Wh][Wl], swizzled
__device__ __align__(16) unsigned short g_atts[COUT * LPATCH * PPSQ]; // bf16 att/nz

// ---------------------------------------------------------------------------
// helpers
// ---------------------------------------------------------------------------
__device__ __forceinline__ uint32_t smem_u32(const void* p) {
    uint32_t a;
    asm("{ .reg .u64 t; cvta.to.shared.u64 t, %1; cvt.u32.u64 %0, t; }"
        : "=r"(a) : "l"(p));
    return a;
}
__device__ __forceinline__ uint32_t pack_bf16x2(float lo, float hi) {
    uint32_t r;
    asm("cvt.rn.bf16x2.f32 %0, %1, %2;" : "=r"(r) : "f"(hi), "f"(lo));
    return r;
}
__device__ __forceinline__ int redux_add(int v) {
    int r;
    asm("redux.sync.add.s32 %0, %1, 0xffffffff;" : "=r"(r) : "r"(v));
    return r;
}
__device__ __forceinline__ void sts64(uint32_t addr, uint32_t a, uint32_t b) {
    asm volatile("st.shared.v2.u32 [%0], {%1, %2};"
                 :: "r"(addr), "r"(a), "r"(b) : "memory");
}
__device__ __forceinline__ void ldsm_x4(uint32_t addr, uint32_t* r) {
    asm volatile("ldmatrix.sync.aligned.m8n8.x4.shared.b16 {%0,%1,%2,%3}, [%4];"
                 : "=r"(r[0]), "=r"(r[1]), "=r"(r[2]), "=r"(r[3]) : "r"(addr));
}
__device__ __forceinline__ void ldsm_x4_t(uint32_t addr, uint32_t* r) {
    asm volatile("ldmatrix.sync.aligned.m8n8.x4.trans.shared.b16 {%0,%1,%2,%3}, [%4];"
                 : "=r"(r[0]), "=r"(r[1]), "=r"(r[2]), "=r"(r[3]) : "r"(addr));
}
__device__ __forceinline__ void mma16816(float* d, const uint32_t* a,
                                         uint32_t b0, uint32_t b1) {
    asm volatile(
        "mma.sync.aligned.m16n8k16.row.col.f32.bf16.bf16.f32 "
        "{%0,%1,%2,%3}, {%4,%5,%6,%7}, {%8,%9}, {%0,%1,%2,%3};"
        : "+f"(d[0]), "+f"(d[1]), "+f"(d[2]), "+f"(d[3])
        : "r"(a[0]), "r"(a[1]), "r"(a[2]), "r"(a[3]), "r"(b0), "r"(b1));
}
__device__ __forceinline__ unsigned short ldg_u16(const unsigned short* p) {
    unsigned short v;
    asm volatile("ld.global.nc.u16 %0, [%1];" : "=h"(v) : "l"(p));
    return v;
}
__device__ __forceinline__ float bf2f(unsigned short v) {
    return __uint_as_float((uint32_t)v << 16);
}
__device__ __forceinline__ float sel4(int r, float a, float b, float c, float d) {
    float v = a;
    v = (r == 1) ? b : v;
    v = (r == 2) ? c : v;
    v = (r == 3) ? d : v;
    return v;
}
// W-tile swizzle (256B rows, verified)
__device__ __forceinline__ uint32_t swz(int row, uint32_t colbyte) {
    return (uint32_t)row * 256u + (colbyte ^ (uint32_t)((row & 7) << 4));
}

// ---------------------------------------------------------------------------
// Prep: W bf16 hi/lo split (swizzled) + att -> bf16(att/nz) into g_atts.
// (verified R7 code)
// ---------------------------------------------------------------------------
__device__ __forceinline__ void process_group(const float4* f, int g, int lane)
{
    int c0 = 0, c1 = 0, c2 = 0, c3 = 0;
#pragma unroll
    for (int p = 0; p < 3; p++) {
        int idx = p * 32 + lane;
        if (idx < 81) {
            float4 q = f[p];
            int e = idx * 4;
            int r0 = (e >= 81) + (e >= 162) + (e >= 243);
            int r3 = (e + 3 >= 81) + (e + 3 >= 162) + (e + 3 >= 243);
            if (r0 == r3) {
                int cnt = (q.x != 0.f) + (q.y != 0.f) + (q.z != 0.f) + (q.w != 0.f);
                c0 += (r0 == 0) ? cnt : 0;
                c1 += (r0 == 1) ? cnt : 0;
                c2 += (r0 == 2) ? cnt : 0;
                c3 += (r0 == 3) ? cnt : 0;
            } else {
                float vv[4] = { q.x, q.y, q.z, q.w };
#pragma unroll
                for (int j = 0; j < 4; j++) {
                    int ej = e + j;
                    int rj = (ej >= 81) + (ej >= 162) + (ej >= 243);
                    int nz = (vv[j] != 0.f);
                    c0 += (rj == 0) ? nz : 0;
                    c1 += (rj == 1) ? nz : 0;
                    c2 += (rj == 2) ? nz : 0;
                    c3 += (rj == 3) ? nz : 0;
                }
            }
        }
    }
    c0 = redux_add(c0); c1 = redux_add(c1);
    c2 = redux_add(c2); c3 = redux_add(c3);
    float i0 = 1.0f / ((float)c0 + 1e-5f);
    float i1 = 1.0f / ((float)c1 + 1e-5f);
    float i2 = 1.0f / ((float)c2 + 1e-5f);
    float i3 = 1.0f / ((float)c3 + 1e-5f);

#pragma unroll
    for (int p = 0; p < 3; p++) {
        int idx = p * 32 + lane;
        if (idx < 81) {
            float4 q = f[p];
            int e = idx * 4;
            int r0 = (e >= 81) + (e >= 162) + (e >= 243);
            int r1 = (e + 1 >= 81) + (e + 1 >= 162) + (e + 1 >= 243);
            int r2 = (e + 2 >= 81) + (e + 2 >= 162) + (e + 2 >= 243);
            int r3 = (e + 3 >= 81) + (e + 3 >= 162) + (e + 3 >= 243);
            float s0 = sel4(r0, i0, i1, i2, i3);
            float s1 = sel4(r1, i0, i1, i2, i3);
            float s2 = sel4(r2, i0, i1, i2, i3);
            float s3 = sel4(r3, i0, i1, i2, i3);
            uint32_t u01 = pack_bf16x2(q.x * s0, q.y * s1);
            uint32_t u23 = pack_bf16x2(q.z * s2, q.w * s3);
            *(uint2*)(g_atts + (size_t)g * 324 + idx * 4) = make_uint2(u01, u23);
        }
    }
}

__global__ __launch_bounds__(256) void prep_kernel(const float* __restrict__ att,
                                                   const float* __restrict__ W)
{
    const int tid = threadIdx.x;
    const int blk = blockIdx.x;

    if (blk < 64) {   // W split
        int idx = blk * 256 + tid;
        int oc = idx >> 7, k = idx & 127;
        float w = W[idx];
        __nv_bfloat16 h = __float2bfloat16(w);
        float hf = __bfloat162float(h);
        __nv_bfloat16 l = __float2bfloat16(w - hf);
        uint32_t off = swz(oc, (uint32_t)(k * 2)) >> 1;
        g_Wsw[off]         = *(unsigned short*)&h;
        g_Wsw[off + 16384] = *(unsigned short*)&l;
    }

    const int wg = (blk * 256 + tid) >> 5;
    const int lane = tid & 31;
    const int g0 = wg * 2;
    const float4* a4a = (const float4*)att + (size_t)g0 * 81;
    const float4* a4b = a4a + 81;

    float4 fa[3], fb[3];
#pragma unroll
    for (int p = 0; p < 3; p++) {
        int idx = p * 32 + lane;
        if (idx < 81) {
            fa[p] = __ldg(a4a + idx);
            fb[p] = __ldg(a4b + idx);
        }
    }
    process_group(fa, g0, lane);
    process_group(fb, g0 + 1, lane);
}

// ---------------------------------------------------------------------------
// Fused persistent kernel: CTA c handles oc-half (c&1), tiles (c>>1)+296k/2.
//   8 warps: ocg = wid&3 (16 oc each -> 64), voxg = wid>>2 (32 vox each -> 64)
//   warp tile: 16 oc x 32 vox.
// ---------------------------------------------------------------------------
struct XFrag { float4 f[8]; };

// warp wid loads k rows [wid*16, wid*16+16) of the 64-vox tile (verified R8)
__device__ __forceinline__ void ldg_tile(const float* __restrict__ x,
                                         int v0, int wid, int lane, XFrag& r)
{
    const int k0 = wid * 16 + (lane >> 4);
    const float* xp = x + (size_t)k0 * NVOX + v0 + (lane & 15) * 4;
#pragma unroll
    for (int i = 0; i < 8; i++)
        r.f[i] = *(const float4*)(xp + (size_t)(2 * i) * NVOX);
}

// buffer: 128 k-rows x 64 vox bf16, 128B rows, chunk xor (k&7) (verified R8)
__device__ __forceinline__ void sts_tile(uint32_t bufH, int wid, int lane,
                                         const XFrag& r)
{
    const int kbase = wid * 16 + (lane >> 4);
    const uint32_t voxb = (uint32_t)((lane & 15) * 8);
#pragma unroll
    for (int i = 0; i < 8; i++) {
        const int k = kbase + 2 * i;
        float4 f = r.f[i];
        uint32_t h01 = pack_bf16x2(f.x, f.y);
        uint32_t h23 = pack_bf16x2(f.z, f.w);
        float h0 = __uint_as_float(h01 << 16);
        float h1 = __uint_as_float(h01 & 0xffff0000u);
        float h2 = __uint_as_float(h23 << 16);
        float h3 = __uint_as_float(h23 & 0xffff0000u);
        uint32_t l01 = pack_bf16x2(f.x - h0, f.y - h1);
        uint32_t l23 = pack_bf16x2(f.z - h2, f.w - h3);
        uint32_t addr = bufH + (uint32_t)k * 128u
                      + (voxb ^ (uint32_t)((k & 7) << 4));
        sts64(addr, h01, h23);
        sts64(addr + 16384, l01, l23);   // xl 16KB after xh
    }
}

__global__ __launch_bounds__(THREADS, 2)
void fused_kernel(const float* __restrict__ x,
                  const float* __restrict__ b,
                  float* __restrict__ out)
{
    extern __shared__ __align__(16) char smem[];
    const uint32_t sbase = smem_u32(smem);
    const int tid  = threadIdx.x;
    const int lane = tid & 31;
    const int wid  = tid >> 5;              // 0..7
    const int ochalf = blockIdx.x & 1;      // oc range [ochalf*64, +64)
    const int tstart = blockIdx.x >> 1;     // vox-tile series start

    // --- load this half's W slice once (32KB) ---
    {
        const float4* WhS = (const float4*)(g_Wsw + ochalf * 8192);
        const float4* WlS = (const float4*)(g_Wsw + 16384 + ochalf * 8192);
        float4* dWh = (float4*)(smem + SM_W);
        float4* dWl = (float4*)(smem + SM_W + 16384);
#pragma unroll
        for (int i = 0; i < 4; i++) {
            dWh[tid + THREADS * i] = WhS[tid + THREADS * i];
            dWl[tid + THREADS * i] = WlS[tid + THREADS * i];
        }
    }

    const int ocb = (wid & 3) * 16;         // local oc base (within 64)
    const int vh  = (wid >> 2) * 32;        // vox group within 64
    const int oc0 = ochalf * 64 + ocb + (lane >> 2);   // global oc row 0
    const int oc1 = oc0 + 8;

    // A-side ldmatrix ([oc][k], 256B rows) — one m16 block + lo at +16KB
    const int aRow = ocb + (lane & 15);
    const uint32_t aSw = (uint32_t)((aRow & 7) << 4);
    const uint32_t aK  = (uint32_t)((lane >> 4) * 16);
    const uint32_t aB  = sbase + SM_W + (uint32_t)aRow * 256u;

    // B-side ldmatrix.trans (128B rows, xor (k&7)) — verified R8
    const int bK = lane & 15;
    uint32_t bOff[2];
#pragma unroll
    for (int nbp = 0; nbp < 2; nbp++) {
        uint32_t voxbyte = (uint32_t)(vh * 2 + nbp * 32 + (lane >> 4) * 16);
        bOff[nbp] = (uint32_t)bK * 128u
                  + (voxbyte ^ ((uint32_t)(bK & 7) << 4));
    }

    const float bias_a = __ldg(b + oc0);
    const float bias_b = __ldg(b + oc1);

    // prologue: tile0 into stage 0
    int t = tstart;
    {
        XFrag r0;
        ldg_tile(x, t * TILE_V, wid, lane, r0);
        sts_tile(sbase, wid, lane, r0);
    }
    __syncthreads();

    int cur = 0;
    while (true) {
        const int tn = t + 148;
        const bool has_next = (tn < NT64);

        // prefetch next x tile into regs (hidden under MMA)
        XFrag rn;
        if (has_next) ldg_tile(x, tn * TILE_V, wid, lane, rn);

        // prefetch epilogue att values for tile t
        unsigned short avr[4][4];
        {
            const unsigned short* A0 = g_atts + (size_t)oc0 * (LPATCH * PPSQ);
            const unsigned short* A1 = g_atts + (size_t)oc1 * (LPATCH * PPSQ);
#pragma unroll
            for (int nb = 0; nb < 4; nb++) {
                int v  = t * TILE_V + vh + 2 * (lane & 3) + nb * 8;
                int d  = v / HWDIM;
                int hw = v - d * HWDIM;
                int id = d / PATCH,  pd = d  - id * PATCH;
                int iw = hw / PATCH, pw = hw - iw * PATCH;
                int l0 = id * NW + iw, p0 = pd * PATCH + pw;
                int l1, p1;
                if (pw == PATCH - 1) { l1 = l0 + 1; p1 = pd * PATCH; }
                else                 { l1 = l0;     p1 = p0 + 1; }
                avr[nb][0] = ldg_u16(A0 + l0 * PPSQ + p0);
                avr[nb][1] = ldg_u16(A0 + l1 * PPSQ + p1);
                avr[nb][2] = ldg_u16(A1 + l0 * PPSQ + p0);
                avr[nb][3] = ldg_u16(A1 + l1 * PPSQ + p1);
            }
        }

        // accumulators, init with bias
        float acc[4][4];
#pragma unroll
        for (int nb = 0; nb < 4; nb++) {
            acc[nb][0] = bias_a; acc[nb][1] = bias_a;
            acc[nb][2] = bias_b; acc[nb][3] = bias_b;
        }

        // MMA over 8 k-steps, 3 split terms, 4 independent acc chains
        const uint32_t bufH = sbase + (uint32_t)cur * 32768u;
        const uint32_t bufL = bufH + 16384u;
#pragma unroll
        for (int ks = 0; ks < 8; ks++) {
            const uint32_t kbA = ((uint32_t)(ks * 32) + aK) ^ aSw;
            uint32_t ah[4], al[4];
            ldsm_x4(aB + kbA,         ah);
            ldsm_x4(aB + 16384 + kbA, al);

            const uint32_t krow = (uint32_t)(ks * 2048);   // 16 rows x 128B
            uint32_t bh0[4], bl0[4], bh1[4], bl1[4];
            ldsm_x4_t(bufH + krow + bOff[0], bh0);
            ldsm_x4_t(bufL + krow + bOff[0], bl0);
            ldsm_x4_t(bufH + krow + bOff[1], bh1);
            ldsm_x4_t(bufL + krow + bOff[1], bl1);

            mma16816(acc[0], ah, bh0[0], bh0[1]);
            mma16816(acc[1], ah, bh0[2], bh0[3]);
            mma16816(acc[2], ah, bh1[0], bh1[1]);
            mma16816(acc[3], ah, bh1[2], bh1[3]);
            mma16816(acc[0], ah, bl0[0], bl0[1]);
            mma16816(acc[1], ah, bl0[2], bl0[3]);
            mma16816(acc[2], ah, bl1[0], bl1[1]);
            mma16816(acc[3], ah, bl1[2], bl1[3]);
            mma16816(acc[0], al, bh0[0], bh0[1]);
            mma16816(acc[1], al, bh0[2], bh0[3]);
            mma16816(acc[2], al, bh1[0], bh1[1]);
            mma16816(acc[3], al, bh1[2], bh1[3]);
        }

        // store next tile into the other stage, then barrier
        if (has_next) sts_tile(sbase + (uint32_t)(cur ^ 1) * 32768u, wid, lane, rn);
        __syncthreads();

        // epilogue: regs + STG only
        const int voxbase = t * TILE_V + vh + 2 * (lane & 3);
        float* o0 = out + (size_t)oc0 * NVOX;
        float* o1 = out + (size_t)oc1 * NVOX;
#pragma unroll
        for (int nb = 0; nb < 4; nb++) {
            const int v = voxbase + nb * 8;
            float a00 = bf2f(avr[nb][0]);
            float a01 = bf2f(avr[nb][1]);
            float a10 = bf2f(avr[nb][2]);
            float a11 = bf2f(avr[nb][3]);

            float y;
            float2 r;
            y = acc[nb][0]; r.x = y * (y + a00 + 1.0f);
            r.x = (r.x >= 0.0f) ? r.x : 0.2f * r.x;
            y = acc[nb][1]; r.y = y * (y + a01 + 1.0f);
            r.y = (r.y >= 0.0f) ? r.y : 0.2f * r.y;
            *(float2*)(o0 + v) = r;

            y = acc[nb][2]; r.x = y * (y + a10 + 1.0f);
            r.x = (r.x >= 0.0f) ? r.x : 0.2f * r.x;
            y = acc[nb][3]; r.y = y * (y + a11 + 1.0f);
            r.y = (r.y >= 0.0f) ? r.y : 0.2f * r.y;
            *(float2*)(o1 + v) = r;
        }

        if (!has_next) break;
        t = tn;
        cur ^= 1;
    }
}

// ---------------------------------------------------------------------------
extern "C" void kernel_launch(void* const* d_in, const int* in_sizes, int n_in,
                              void* d_out, int out_size)
{
    (void)in_sizes; (void)n_in; (void)out_size;
    const float* x   = (const float*)d_in[0];
    const float* att = (const float*)d_in[1];
    const float* W   = (const float*)d_in[2];
    const float* b   = (const float*)d_in[3];
    float* out = (float*)d_out;

    prep_kernel<<<4608, 256>>>(att, W);

    cudaFuncSetAttribute(fused_kernel,
                         cudaFuncAttributeMaxDynamicSharedMemorySize,
                         SMEM_TOTAL);
    fused_kernel<<<GRID, THREADS, SMEM_TOTAL>>>(x, b, out);
}